// round 1
// baseline (speedup 1.0000x reference)
#include <cuda_runtime.h>
#include <math.h>

// Problem constants
#define BB   2
#define SS   2048
#define DD   2048
#define NH   16
#define NKV  4
#define HD   128
#define EHEADS (NH + 2*NKV)          // 24
#define QKVE (EHEADS * HD)           // 3072

// ---------------- scratch (device globals; no allocation allowed) ----------
__device__ float g_qkv[(size_t)BB * SS * QKVE];          // [4096][3072]
__device__ float g_q  [(size_t)BB * NH  * SS * HD];      // [B][NH][S][HD]
__device__ float g_k  [(size_t)BB * NKV * SS * HD];      // [B][NKV][S][HD]
__device__ float g_v  [(size_t)BB * NKV * SS * HD];      // [B][NKV][S][HD]
__device__ float g_y  [(size_t)BB * SS * DD];            // [4096][2048]

// ---------------- packed f32x2 helpers -------------------------------------
__device__ __forceinline__ unsigned long long pack2(float x) {
    unsigned long long r;
    asm("mov.b64 %0, {%1, %1};" : "=l"(r) : "f"(x));
    return r;
}
__device__ __forceinline__ void fma2(unsigned long long& c,
                                     unsigned long long a,
                                     unsigned long long b) {
    asm("fma.rn.f32x2 %0, %1, %2, %0;" : "+l"(c) : "l"(a), "l"(b));
}
__device__ __forceinline__ float2 unpack2(unsigned long long v) {
    float2 r;
    asm("mov.b64 {%0, %1}, %2;" : "=f"(r.x), "=f"(r.y) : "l"(v));
    return r;
}

// ---------------- GEMM: C[M,N] = A[M,K] * B[N,K]^T  (both K-major) ----------
#define GBM 128
#define GBN 128
#define GBK 16
#define GAS (GBM + 4)   // padded row stride (floats); 132*4B = 528, 16B aligned

__global__ void __launch_bounds__(256) gemm_nt(const float* __restrict__ A,
                                               const float* __restrict__ B,
                                               float* __restrict__ C,
                                               int M, int N, int K)
{
    __shared__ __align__(16) float As[GBK * GAS];
    __shared__ __align__(16) float Bs[GBK * GAS];

    const int tid  = threadIdx.x;
    const int bm   = blockIdx.y * GBM;
    const int bn   = blockIdx.x * GBN;
    const int lrow = tid >> 2;          // 0..63
    const int lk4  = (tid & 3) << 2;    // 0,4,8,12

    const float* Ap = A + (size_t)(bm + lrow) * K + lk4;
    const float* Bp = B + (size_t)(bn + lrow) * K + lk4;
    const size_t rowoff = (size_t)64 * K;

    unsigned long long acc[8][4];
    #pragma unroll
    for (int i = 0; i < 8; i++)
        #pragma unroll
        for (int j = 0; j < 4; j++)
            acc[i][j] = 0ull;

    const int ty = tid >> 4, tx = tid & 15;
    const int nk = K / GBK;

    float4 a0 = *(const float4*)Ap;
    float4 a1 = *(const float4*)(Ap + rowoff);
    float4 b0 = *(const float4*)Bp;
    float4 b1 = *(const float4*)(Bp + rowoff);

    for (int t = 0; t < nk; ++t) {
        As[(lk4+0)*GAS + lrow]      = a0.x;
        As[(lk4+1)*GAS + lrow]      = a0.y;
        As[(lk4+2)*GAS + lrow]      = a0.z;
        As[(lk4+3)*GAS + lrow]      = a0.w;
        As[(lk4+0)*GAS + lrow + 64] = a1.x;
        As[(lk4+1)*GAS + lrow + 64] = a1.y;
        As[(lk4+2)*GAS + lrow + 64] = a1.z;
        As[(lk4+3)*GAS + lrow + 64] = a1.w;
        Bs[(lk4+0)*GAS + lrow]      = b0.x;
        Bs[(lk4+1)*GAS + lrow]      = b0.y;
        Bs[(lk4+2)*GAS + lrow]      = b0.z;
        Bs[(lk4+3)*GAS + lrow]      = b0.w;
        Bs[(lk4+0)*GAS + lrow + 64] = b1.x;
        Bs[(lk4+1)*GAS + lrow + 64] = b1.y;
        Bs[(lk4+2)*GAS + lrow + 64] = b1.z;
        Bs[(lk4+3)*GAS + lrow + 64] = b1.w;
        __syncthreads();

        if (t + 1 < nk) {
            Ap += GBK; Bp += GBK;
            a0 = *(const float4*)Ap;
            a1 = *(const float4*)(Ap + rowoff);
            b0 = *(const float4*)Bp;
            b1 = *(const float4*)(Bp + rowoff);
        }

        #pragma unroll
        for (int k = 0; k < GBK; ++k) {
            const float* arow = &As[k*GAS + ty*8];
            float4 af0 = *(const float4*)(arow);
            float4 af1 = *(const float4*)(arow + 4);
            const float* brow = &Bs[k*GAS + tx*8];
            ulonglong2 bl0 = *(const ulonglong2*)(brow);
            ulonglong2 bl1 = *(const ulonglong2*)(brow + 4);

            unsigned long long av[8];
            av[0] = pack2(af0.x); av[1] = pack2(af0.y);
            av[2] = pack2(af0.z); av[3] = pack2(af0.w);
            av[4] = pack2(af1.x); av[5] = pack2(af1.y);
            av[6] = pack2(af1.z); av[7] = pack2(af1.w);
            unsigned long long bv[4] = {bl0.x, bl0.y, bl1.x, bl1.y};

            #pragma unroll
            for (int i = 0; i < 8; i++)
                #pragma unroll
                for (int jp = 0; jp < 4; jp++)
                    fma2(acc[i][jp], av[i], bv[jp]);
        }
        __syncthreads();
    }

    #pragma unroll
    for (int i = 0; i < 8; i++) {
        float2 c0 = unpack2(acc[i][0]);
        float2 c1 = unpack2(acc[i][1]);
        float2 c2 = unpack2(acc[i][2]);
        float2 c3 = unpack2(acc[i][3]);
        float4 lo = make_float4(c0.x, c0.y, c1.x, c1.y);
        float4 hi = make_float4(c2.x, c2.y, c3.x, c3.y);
        float* cp = C + (size_t)(bm + ty*8 + i) * N + bn + tx*8;
        *(float4*)cp       = lo;
        *(float4*)(cp + 4) = hi;
    }
}

// ---------------- RMSNorm + RoPE + scatter to [B,H,S,HD] --------------------
__global__ void __launch_bounds__(256) norm_rope(const float* __restrict__ qkv,
                                                 const float* __restrict__ freqs,
                                                 const float* __restrict__ qw,
                                                 const float* __restrict__ kw,
                                                 float* __restrict__ qo,
                                                 float* __restrict__ ko,
                                                 float* __restrict__ vo)
{
    const int n    = blockIdx.x;        // b*S + s
    const int b    = n >> 11;
    const int s    = n & 2047;
    const int wid  = threadIdx.x >> 5;
    const int lane = threadIdx.x & 31;

    for (int h = wid; h < EHEADS; h += 8) {
        const float* src = qkv + (size_t)n * QKVE + h * HD;
        float4 v = *(const float4*)(src + lane*4);
        if (h < NH + NKV) {
            float ss = v.x*v.x + v.y*v.y + v.z*v.z + v.w*v.w;
            #pragma unroll
            for (int off = 16; off >= 1; off >>= 1)
                ss += __shfl_xor_sync(0xffffffffu, ss, off);
            float inv = rsqrtf(ss * (1.0f / HD) + 1e-6f);
            const float* w = (h < NH) ? qw : kw;
            float4 wv = *(const float4*)(w + lane*4);
            float x0 = v.x * inv * wv.x;
            float x1 = v.y * inv * wv.y;
            float x2 = v.z * inv * wv.z;
            float x3 = v.w * inv * wv.w;
            float2 f0 = *(const float2*)(freqs + (size_t)(s*64 + lane*2)     * 2);
            float2 f1 = *(const float2*)(freqs + (size_t)(s*64 + lane*2 + 1) * 2);
            float4 o;
            o.x = x0*f0.x - x1*f0.y;
            o.y = x1*f0.x + x0*f0.y;
            o.z = x2*f1.x - x3*f1.y;
            o.w = x3*f1.x + x2*f1.y;
            float* dst;
            if (h < NH) dst = qo + (((size_t)b*NH  + h)        * SS + s) * HD;
            else        dst = ko + (((size_t)b*NKV + (h - NH)) * SS + s) * HD;
            *(float4*)(dst + lane*4) = o;
        } else {
            float* dst = vo + (((size_t)b*NKV + (h - NH - NKV)) * SS + s) * HD;
            *(float4*)(dst + lane*4) = v;
        }
    }
}

// ---------------- Flash attention (causal, GQA) -----------------------------
// BM=BN=64, 256 threads (ty 0..15 = 4 q-rows, tx 0..15 = 4 score cols / 8 o cols)
#define FQS 68    // padded r-stride for transposed Q/K/P tiles
#define FVS 132   // padded d-stride for V tile
#define FLASH_SMEM ((128*FQS + 128*FQS + 64*FVS + 64*FQS) * 4)

__global__ void __launch_bounds__(256) flash_kernel(const float* __restrict__ Q,
                                                    const float* __restrict__ Kt,
                                                    const float* __restrict__ V,
                                                    float* __restrict__ Y)
{
    extern __shared__ __align__(16) float sm[];
    float* Qs = sm;                    // [d][r]  128 x 68
    float* Ks = Qs + 128*FQS;          // [d][c]  128 x 68
    float* Vs = Ks + 128*FQS;          // [kk][d]  64 x 132
    float* Ps = Vs + 64*FVS;           // [c][r]   64 x 68

    const int tid = threadIdx.x;
    const int qb  = gridDim.x - 1 - blockIdx.x;   // long blocks first
    const int h   = blockIdx.y;
    const int b   = blockIdx.z;
    const int q0  = qb * 64;

    const float* qptr  = Q  + (((size_t)b*NH  + h)        * SS + q0) * HD;
    const float* kbase = Kt + (((size_t)b*NKV + (h >> 2)) * SS)      * HD;
    const float* vbase = V  + (((size_t)b*NKV + (h >> 2)) * SS)      * HD;
    const float scale  = 0.08838834764831845f;   // 1/sqrt(128)

    // Q tile, transposed + pre-scaled
    for (int idx = tid; idx < 64*32; idx += 256) {
        int r = idx >> 5, d4 = (idx & 31) << 2;
        float4 v = *(const float4*)(qptr + (size_t)r*HD + d4);
        Qs[(d4+0)*FQS + r] = v.x * scale;
        Qs[(d4+1)*FQS + r] = v.y * scale;
        Qs[(d4+2)*FQS + r] = v.z * scale;
        Qs[(d4+3)*FQS + r] = v.w * scale;
    }

    const int ty = tid >> 4, tx = tid & 15;
    float o[4][8];
    float m[4], l[4];
    #pragma unroll
    for (int i = 0; i < 4; i++) {
        m[i] = -1e30f; l[i] = 0.f;
        #pragma unroll
        for (int j = 0; j < 8; j++) o[i][j] = 0.f;
    }
    __syncthreads();

    const int nkb = qb + 1;
    for (int kb = 0; kb < nkb; ++kb) {
        const int k0 = kb * 64;
        for (int idx = tid; idx < 64*32; idx += 256) {
            int r = idx >> 5, d4 = (idx & 31) << 2;
            float4 kv = *(const float4*)(kbase + (size_t)(k0 + r)*HD + d4);
            Ks[(d4+0)*FQS + r] = kv.x;
            Ks[(d4+1)*FQS + r] = kv.y;
            Ks[(d4+2)*FQS + r] = kv.z;
            Ks[(d4+3)*FQS + r] = kv.w;
            float4 vv = *(const float4*)(vbase + (size_t)(k0 + r)*HD + d4);
            *(float4*)&Vs[r*FVS + d4] = vv;
        }
        __syncthreads();

        float s[4][4];
        #pragma unroll
        for (int i = 0; i < 4; i++)
            #pragma unroll
            for (int j = 0; j < 4; j++) s[i][j] = 0.f;

        #pragma unroll 4
        for (int d = 0; d < 128; ++d) {
            float4 qa = *(const float4*)&Qs[d*FQS + ty*4];
            float4 kk = *(const float4*)&Ks[d*FQS + tx*4];
            float qv[4] = {qa.x, qa.y, qa.z, qa.w};
            float kv[4] = {kk.x, kk.y, kk.z, kk.w};
            #pragma unroll
            for (int i = 0; i < 4; i++)
                #pragma unroll
                for (int j = 0; j < 4; j++)
                    s[i][j] += qv[i] * kv[j];
        }

        if (kb == qb) {   // diagonal tile: causal mask
            #pragma unroll
            for (int i = 0; i < 4; i++)
                #pragma unroll
                for (int j = 0; j < 4; j++)
                    if (k0 + tx*4 + j > q0 + ty*4 + i) s[i][j] = -1e30f;
        }

        // online softmax, row group = 16 threads sharing ty (lane segment of 16)
        #pragma unroll
        for (int i = 0; i < 4; i++) {
            float mx = fmaxf(fmaxf(s[i][0], s[i][1]), fmaxf(s[i][2], s[i][3]));
            #pragma unroll
            for (int off = 8; off >= 1; off >>= 1)
                mx = fmaxf(mx, __shfl_xor_sync(0xffffffffu, mx, off, 16));
            float mn   = fmaxf(m[i], mx);
            float corr = __expf(m[i] - mn);
            m[i] = mn;
            float rs = 0.f;
            #pragma unroll
            for (int j = 0; j < 4; j++) {
                float p = __expf(s[i][j] - mn);
                s[i][j] = p;
                rs += p;
            }
            #pragma unroll
            for (int off = 8; off >= 1; off >>= 1)
                rs += __shfl_xor_sync(0xffffffffu, rs, off, 16);
            l[i] = l[i] * corr + rs;
            #pragma unroll
            for (int j = 0; j < 8; j++) o[i][j] *= corr;
        }

        #pragma unroll
        for (int i = 0; i < 4; i++)
            #pragma unroll
            for (int j = 0; j < 4; j++)
                Ps[(tx*4 + j)*FQS + ty*4 + i] = s[i][j];
        __syncthreads();

        // O += P * V
        #pragma unroll 2
        for (int kk2 = 0; kk2 < 64; ++kk2) {
            float4 pv = *(const float4*)&Ps[kk2*FQS + ty*4];
            float p4[4] = {pv.x, pv.y, pv.z, pv.w};
            float4 v0 = *(const float4*)&Vs[kk2*FVS + tx*8];
            float4 v1 = *(const float4*)&Vs[kk2*FVS + tx*8 + 4];
            float vv[8] = {v0.x, v0.y, v0.z, v0.w, v1.x, v1.y, v1.z, v1.w};
            #pragma unroll
            for (int i = 0; i < 4; i++)
                #pragma unroll
                for (int j = 0; j < 8; j++)
                    o[i][j] += p4[i] * vv[j];
        }
        __syncthreads();
    }

    #pragma unroll
    for (int i = 0; i < 4; i++) {
        float inv = 1.0f / l[i];
        int row = q0 + ty*4 + i;
        float* yp = Y + ((size_t)(b*SS + row)) * DD + h*HD + tx*8;
        float4 r0 = make_float4(o[i][0]*inv, o[i][1]*inv, o[i][2]*inv, o[i][3]*inv);
        float4 r1 = make_float4(o[i][4]*inv, o[i][5]*inv, o[i][6]*inv, o[i][7]*inv);
        *(float4*)yp       = r0;
        *(float4*)(yp + 4) = r1;
    }
}

// ---------------- launch ----------------------------------------------------
extern "C" void kernel_launch(void* const* d_in, const int* in_sizes, int n_in,
                              void* d_out, int out_size)
{
    const float* x     = (const float*)d_in[0];
    const float* freqs = (const float*)d_in[1];
    const float* wqkv  = (const float*)d_in[2];
    const float* wo    = (const float*)d_in[3];
    const float* qw    = (const float*)d_in[4];
    const float* kw    = (const float*)d_in[5];
    float* out = (float*)d_out;

    float *p_qkv, *p_q, *p_k, *p_v, *p_y;
    cudaGetSymbolAddress((void**)&p_qkv, g_qkv);
    cudaGetSymbolAddress((void**)&p_q,   g_q);
    cudaGetSymbolAddress((void**)&p_k,   g_k);
    cudaGetSymbolAddress((void**)&p_v,   g_v);
    cudaGetSymbolAddress((void**)&p_y,   g_y);

    // 1) QKV projection: [4096,3072] = x[4096,2048] * wqkv[3072,2048]^T
    gemm_nt<<<dim3(QKVE/GBN, (BB*SS)/GBM), 256>>>(x, wqkv, p_qkv,
                                                  BB*SS, QKVE, DD);

    // 2) RMSNorm + RoPE + layout transform
    norm_rope<<<BB*SS, 256>>>(p_qkv, freqs, qw, kw, p_q, p_k, p_v);

    // 3) Flash attention (causal, GQA)
    cudaFuncSetAttribute(flash_kernel,
                         cudaFuncAttributeMaxDynamicSharedMemorySize, FLASH_SMEM);
    flash_kernel<<<dim3(SS/64, NH, BB), 256, FLASH_SMEM>>>(p_q, p_k, p_v, p_y);

    // 4) Output projection: out[4096,2048] = y[4096,2048] * wo[2048,2048]^T
    gemm_nt<<<dim3(DD/GBN, (BB*SS)/GBM), 256>>>(p_y, wo, out,
                                                BB*SS, DD, NH*HD);
}

// round 2
// speedup vs baseline: 1.3816x; 1.3816x over previous
#include <cuda_runtime.h>
#include <math.h>

// Problem constants
#define BB   2
#define SS   2048
#define DD   2048
#define NH   16
#define NKV  4
#define HD   128
#define EHEADS (NH + 2*NKV)          // 24
#define QKVE (EHEADS * HD)           // 3072

// ---------------- scratch (device globals; no allocation allowed) ----------
__device__ float g_qkv[(size_t)BB * SS * QKVE];          // [4096][3072]
__device__ float g_qt [(size_t)BB * NH  * HD * SS];      // [B][NH][HD][S]  (transposed, pre-scaled)
__device__ float g_kt [(size_t)BB * NKV * HD * SS];      // [B][NKV][HD][S] (transposed)
__device__ float g_y  [(size_t)BB * SS * DD];            // [4096][2048]

// ---------------- packed f32x2 helpers -------------------------------------
__device__ __forceinline__ unsigned long long pack2(float x) {
    unsigned long long r;
    asm("mov.b64 %0, {%1, %1};" : "=l"(r) : "f"(x));
    return r;
}
__device__ __forceinline__ void fma2(unsigned long long& c,
                                     unsigned long long a,
                                     unsigned long long b) {
    asm("fma.rn.f32x2 %0, %1, %2, %0;" : "+l"(c) : "l"(a), "l"(b));
}
__device__ __forceinline__ void mul2(unsigned long long& c, unsigned long long a) {
    asm("mul.rn.f32x2 %0, %0, %1;" : "+l"(c) : "l"(a));
}
__device__ __forceinline__ float2 unpack2(unsigned long long v) {
    float2 r;
    asm("mov.b64 {%0, %1}, %2;" : "=f"(r.x), "=f"(r.y) : "l"(v));
    return r;
}
__device__ __forceinline__ float ex2f(float x) {
    float y;
    asm("ex2.approx.ftz.f32 %0, %1;" : "=f"(y) : "f"(x));
    return y;
}

// ---------------- GEMM: C[M,N] = A[M,K] * B[N,K]^T  (both K-major) ----------
#define GBM 128
#define GBN 128
#define GBK 16
#define GAS (GBM + 4)   // padded row stride (floats)

__global__ void __launch_bounds__(256) gemm_nt(const float* __restrict__ A,
                                               const float* __restrict__ B,
                                               float* __restrict__ C,
                                               int M, int N, int K)
{
    __shared__ __align__(16) float As[2][GBK * GAS];
    __shared__ __align__(16) float Bs[2][GBK * GAS];

    const int tid  = threadIdx.x;
    const int bm   = blockIdx.y * GBM;
    const int bn   = blockIdx.x * GBN;
    const int lrow = tid >> 2;          // 0..63
    const int lk4  = (tid & 3) << 2;    // 0,4,8,12

    const float* Ap = A + (size_t)(bm + lrow) * K + lk4;
    const float* Bp = B + (size_t)(bn + lrow) * K + lk4;
    const size_t rowoff = (size_t)64 * K;

    unsigned long long acc[8][4];
    #pragma unroll
    for (int i = 0; i < 8; i++)
        #pragma unroll
        for (int j = 0; j < 4; j++)
            acc[i][j] = 0ull;

    const int ty = tid >> 4, tx = tid & 15;
    const int nk = K / GBK;

    float4 a0 = *(const float4*)Ap;
    float4 a1 = *(const float4*)(Ap + rowoff);
    float4 b0 = *(const float4*)Bp;
    float4 b1 = *(const float4*)(Bp + rowoff);

    // fill buffer 0
    {
        float* Aw = As[0]; float* Bw = Bs[0];
        Aw[(lk4+0)*GAS + lrow]      = a0.x;
        Aw[(lk4+1)*GAS + lrow]      = a0.y;
        Aw[(lk4+2)*GAS + lrow]      = a0.z;
        Aw[(lk4+3)*GAS + lrow]      = a0.w;
        Aw[(lk4+0)*GAS + lrow + 64] = a1.x;
        Aw[(lk4+1)*GAS + lrow + 64] = a1.y;
        Aw[(lk4+2)*GAS + lrow + 64] = a1.z;
        Aw[(lk4+3)*GAS + lrow + 64] = a1.w;
        Bw[(lk4+0)*GAS + lrow]      = b0.x;
        Bw[(lk4+1)*GAS + lrow]      = b0.y;
        Bw[(lk4+2)*GAS + lrow]      = b0.z;
        Bw[(lk4+3)*GAS + lrow]      = b0.w;
        Bw[(lk4+0)*GAS + lrow + 64] = b1.x;
        Bw[(lk4+1)*GAS + lrow + 64] = b1.y;
        Bw[(lk4+2)*GAS + lrow + 64] = b1.z;
        Bw[(lk4+3)*GAS + lrow + 64] = b1.w;
    }
    __syncthreads();

    for (int t = 0; t < nk; ++t) {
        const int cur = t & 1;
        if (t + 1 < nk) {
            Ap += GBK; Bp += GBK;
            a0 = *(const float4*)Ap;
            a1 = *(const float4*)(Ap + rowoff);
            b0 = *(const float4*)Bp;
            b1 = *(const float4*)(Bp + rowoff);
        }

        const float* Ar = As[cur];
        const float* Br = Bs[cur];
        #pragma unroll
        for (int k = 0; k < GBK; ++k) {
            const float* arow = &Ar[k*GAS + ty*8];
            float4 af0 = *(const float4*)(arow);
            float4 af1 = *(const float4*)(arow + 4);
            ulonglong2 bl0 = *(const ulonglong2*)&Br[k*GAS + tx*4];
            ulonglong2 bl1 = *(const ulonglong2*)&Br[k*GAS + 64 + tx*4];

            unsigned long long av[8];
            av[0] = pack2(af0.x); av[1] = pack2(af0.y);
            av[2] = pack2(af0.z); av[3] = pack2(af0.w);
            av[4] = pack2(af1.x); av[5] = pack2(af1.y);
            av[6] = pack2(af1.z); av[7] = pack2(af1.w);
            unsigned long long bv[4] = {bl0.x, bl0.y, bl1.x, bl1.y};

            #pragma unroll
            for (int i = 0; i < 8; i++)
                #pragma unroll
                for (int jp = 0; jp < 4; jp++)
                    fma2(acc[i][jp], av[i], bv[jp]);
        }

        if (t + 1 < nk) {
            const int nxt = (t + 1) & 1;
            float* Aw = As[nxt]; float* Bw = Bs[nxt];
            Aw[(lk4+0)*GAS + lrow]      = a0.x;
            Aw[(lk4+1)*GAS + lrow]      = a0.y;
            Aw[(lk4+2)*GAS + lrow]      = a0.z;
            Aw[(lk4+3)*GAS + lrow]      = a0.w;
            Aw[(lk4+0)*GAS + lrow + 64] = a1.x;
            Aw[(lk4+1)*GAS + lrow + 64] = a1.y;
            Aw[(lk4+2)*GAS + lrow + 64] = a1.z;
            Aw[(lk4+3)*GAS + lrow + 64] = a1.w;
            Bw[(lk4+0)*GAS + lrow]      = b0.x;
            Bw[(lk4+1)*GAS + lrow]      = b0.y;
            Bw[(lk4+2)*GAS + lrow]      = b0.z;
            Bw[(lk4+3)*GAS + lrow]      = b0.w;
            Bw[(lk4+0)*GAS + lrow + 64] = b1.x;
            Bw[(lk4+1)*GAS + lrow + 64] = b1.y;
            Bw[(lk4+2)*GAS + lrow + 64] = b1.z;
            Bw[(lk4+3)*GAS + lrow + 64] = b1.w;
        }
        __syncthreads();
    }

    #pragma unroll
    for (int i = 0; i < 8; i++) {
        float2 c0 = unpack2(acc[i][0]);
        float2 c1 = unpack2(acc[i][1]);
        float2 c2 = unpack2(acc[i][2]);
        float2 c3 = unpack2(acc[i][3]);
        float4 lo = make_float4(c0.x, c0.y, c1.x, c1.y);
        float4 hi = make_float4(c2.x, c2.y, c3.x, c3.y);
        float* cp = C + (size_t)(bm + ty*8 + i) * N + bn;
        *(float4*)(cp + tx*4)      = lo;
        *(float4*)(cp + 64 + tx*4) = hi;
    }
}

// ---------------- RMSNorm + RoPE + transpose to [B,H][HD][S] ----------------
// Q is additionally pre-scaled by (1/sqrt(HD)) * log2(e) so flash can use ex2.
#define QSCALE 0.12751943f
__global__ void __launch_bounds__(256) norm_rope_t(const float* __restrict__ qkv,
                                                   const float* __restrict__ freqs,
                                                   const float* __restrict__ qw,
                                                   const float* __restrict__ kw,
                                                   float* __restrict__ qt,
                                                   float* __restrict__ kt)
{
    __shared__ float st[128 * 33];
    const int s0   = blockIdx.x * 32;
    const int h    = blockIdx.y;          // 0..NH-1 = q heads, NH..NH+NKV-1 = k heads
    const int b    = blockIdx.z;
    const int w    = threadIdx.x >> 5;
    const int lane = threadIdx.x & 31;
    const bool isq = (h < NH);
    const float fold = isq ? QSCALE : 1.0f;
    const float* wn  = isq ? qw : kw;
    const float4 wv  = *(const float4*)(wn + lane*4);

    #pragma unroll
    for (int ii = 0; ii < 4; ii++) {
        const int sl = w*4 + ii;
        const int s  = s0 + sl;
        const float* src = qkv + ((size_t)(b*SS + s)) * QKVE + h * HD;
        float4 v = *(const float4*)(src + lane*4);
        float ssum = v.x*v.x + v.y*v.y + v.z*v.z + v.w*v.w;
        #pragma unroll
        for (int off = 16; off >= 1; off >>= 1)
            ssum += __shfl_xor_sync(0xffffffffu, ssum, off);
        float inv = rsqrtf(ssum * (1.0f / HD) + 1e-6f) * fold;
        float x0 = v.x * inv * wv.x;
        float x1 = v.y * inv * wv.y;
        float x2 = v.z * inv * wv.z;
        float x3 = v.w * inv * wv.w;
        float4 f = *(const float4*)(freqs + (size_t)s*128 + lane*4);
        float o0 = x0*f.x - x1*f.y;
        float o1 = x1*f.x + x0*f.y;
        float o2 = x2*f.z - x3*f.w;
        float o3 = x3*f.z + x2*f.w;
        st[(lane*4+0)*33 + sl] = o0;
        st[(lane*4+1)*33 + sl] = o1;
        st[(lane*4+2)*33 + sl] = o2;
        st[(lane*4+3)*33 + sl] = o3;
    }
    __syncthreads();

    float* dst = isq ? (qt + ((size_t)(b*NH  + h))      * HD * SS)
                     : (kt + ((size_t)(b*NKV + h - NH)) * HD * SS);
    #pragma unroll
    for (int it = 0; it < 4; it++) {
        int lin = threadIdx.x + it*256;
        int d   = lin >> 3;
        int sl4 = (lin & 7) << 2;
        float4 o = make_float4(st[d*33 + sl4 + 0], st[d*33 + sl4 + 1],
                               st[d*33 + sl4 + 2], st[d*33 + sl4 + 3]);
        *(float4*)(dst + (size_t)d*SS + s0 + sl4) = o;
    }
}

// ---------------- Flash attention (causal, GQA), f32x2-packed ----------------
#define FQS 68    // r-stride for Qs/Ks/Ps ([d][r] / [c][r])
#define FVS 132   // d-stride for Vs ([kk][d])
#define FLASH_SMEM ((128*FQS + 128*FQS + 64*FVS + 64*FQS) * 4)

__global__ void __launch_bounds__(256) flash_kernel(const float* __restrict__ Qt,
                                                    const float* __restrict__ Kt,
                                                    const float* __restrict__ qkv,
                                                    float* __restrict__ Y)
{
    extern __shared__ __align__(16) float sm[];
    float* Qs = sm;                    // [d][r]  128 x 68 (pre-scaled by QSCALE)
    float* Ks = Qs + 128*FQS;          // [d][c]  128 x 68
    float* Vs = Ks + 128*FQS;          // [kk][d]  64 x 132
    float* Ps = Vs + 64*FVS;           // [c][r]   64 x 68

    const int tid = threadIdx.x;
    const int qb  = gridDim.x - 1 - blockIdx.x;   // long blocks first
    const int h   = blockIdx.y;
    const int b   = blockIdx.z;
    const int q0  = qb * 64;

    const float* qsrc = Qt  + ((size_t)(b*NH  + h)        * HD) * SS + q0;
    const float* ksrc = Kt  + ((size_t)(b*NKV + (h >> 2)) * HD) * SS;
    const float* vsrc = qkv + ((size_t)b*SS) * QKVE + (NH + NKV + (h >> 2)) * HD;

    // Q tile: already transposed in global, direct coalesced copy
    #pragma unroll
    for (int it = 0; it < 8; it++) {
        int lin = tid + it*256;
        int d   = lin >> 4;
        int rr  = (lin & 15) << 2;
        *(float4*)&Qs[d*FQS + rr] = *(const float4*)(qsrc + (size_t)d*SS + rr);
    }

    const int ty = tid >> 4, tx = tid & 15;
    unsigned long long o2[4][4];   // [row i][col-pair]: pairs (tx*4+0,1),(tx*4+2,3),(64+tx*4+0,1),(64+tx*4+2,3)
    float m[4], l[4];
    #pragma unroll
    for (int i = 0; i < 4; i++) {
        m[i] = -1e30f; l[i] = 0.f;
        #pragma unroll
        for (int j = 0; j < 4; j++) o2[i][j] = 0ull;
    }
    __syncthreads();

    const int nkb = qb + 1;
    for (int kb = 0; kb < nkb; ++kb) {
        const int k0 = kb * 64;
        // K tile (transposed global → direct copy), V tile (natural)
        #pragma unroll
        for (int it = 0; it < 8; it++) {
            int lin = tid + it*256;
            int d   = lin >> 4;
            int rr  = (lin & 15) << 2;
            *(float4*)&Ks[d*FQS + rr] = *(const float4*)(ksrc + (size_t)d*SS + k0 + rr);
            int r  = lin >> 5;
            int d4 = (lin & 31) << 2;
            *(float4*)&Vs[r*FVS + d4] = *(const float4*)(vsrc + (size_t)(k0 + r)*QKVE + d4);
        }
        __syncthreads();

        // QK^T: acc0 = rows(0,1), acc1 = rows(2,3), per col j
        unsigned long long acc0[4], acc1[4];
        #pragma unroll
        for (int j = 0; j < 4; j++) { acc0[j] = 0ull; acc1[j] = 0ull; }

        #pragma unroll 2
        for (int d = 0; d < 128; ++d) {
            ulonglong2 qp = *(const ulonglong2*)&Qs[d*FQS + ty*4];
            float4 kk4 = *(const float4*)&Ks[d*FQS + tx*4];
            unsigned long long b0 = pack2(kk4.x), b1 = pack2(kk4.y);
            unsigned long long b2 = pack2(kk4.z), b3 = pack2(kk4.w);
            fma2(acc0[0], qp.x, b0); fma2(acc1[0], qp.y, b0);
            fma2(acc0[1], qp.x, b1); fma2(acc1[1], qp.y, b1);
            fma2(acc0[2], qp.x, b2); fma2(acc1[2], qp.y, b2);
            fma2(acc0[3], qp.x, b3); fma2(acc1[3], qp.y, b3);
        }

        float s[4][4];
        #pragma unroll
        for (int j = 0; j < 4; j++) {
            float2 p01 = unpack2(acc0[j]);
            float2 p23 = unpack2(acc1[j]);
            s[0][j] = p01.x; s[1][j] = p01.y;
            s[2][j] = p23.x; s[3][j] = p23.y;
        }

        if (kb == qb) {   // diagonal tile: causal mask (log2 domain, -1e30 = -inf)
            #pragma unroll
            for (int i = 0; i < 4; i++)
                #pragma unroll
                for (int j = 0; j < 4; j++)
                    if (k0 + tx*4 + j > q0 + ty*4 + i) s[i][j] = -1e30f;
        }

        // online softmax in log2 domain (Q pre-scaled by scale*log2e)
        #pragma unroll
        for (int i = 0; i < 4; i++) {
            float mx = fmaxf(fmaxf(s[i][0], s[i][1]), fmaxf(s[i][2], s[i][3]));
            #pragma unroll
            for (int off = 8; off >= 1; off >>= 1)
                mx = fmaxf(mx, __shfl_xor_sync(0xffffffffu, mx, off, 16));
            float mn   = fmaxf(m[i], mx);
            float corr = ex2f(m[i] - mn);
            m[i] = mn;
            float rs = 0.f;
            #pragma unroll
            for (int j = 0; j < 4; j++) {
                float p = ex2f(s[i][j] - mn);
                s[i][j] = p;
                rs += p;
            }
            #pragma unroll
            for (int off = 8; off >= 1; off >>= 1)
                rs += __shfl_xor_sync(0xffffffffu, rs, off, 16);
            l[i] = l[i] * corr + rs;
            unsigned long long c2 = pack2(corr);
            #pragma unroll
            for (int j = 0; j < 4; j++) mul2(o2[i][j], c2);
        }

        // store P transposed [c][r], float4 over rows
        #pragma unroll
        for (int j = 0; j < 4; j++) {
            float4 pi = make_float4(s[0][j], s[1][j], s[2][j], s[3][j]);
            *(float4*)&Ps[(tx*4 + j)*FQS + ty*4] = pi;
        }
        __syncthreads();

        // O += P * V
        #pragma unroll 2
        for (int kk = 0; kk < 64; ++kk) {
            float4 pv = *(const float4*)&Ps[kk*FQS + ty*4];
            unsigned long long p0 = pack2(pv.x), p1 = pack2(pv.y);
            unsigned long long p2 = pack2(pv.z), p3 = pack2(pv.w);
            ulonglong2 va = *(const ulonglong2*)&Vs[kk*FVS + tx*4];
            ulonglong2 vb = *(const ulonglong2*)&Vs[kk*FVS + 64 + tx*4];
            fma2(o2[0][0], p0, va.x); fma2(o2[0][1], p0, va.y);
            fma2(o2[0][2], p0, vb.x); fma2(o2[0][3], p0, vb.y);
            fma2(o2[1][0], p1, va.x); fma2(o2[1][1], p1, va.y);
            fma2(o2[1][2], p1, vb.x); fma2(o2[1][3], p1, vb.y);
            fma2(o2[2][0], p2, va.x); fma2(o2[2][1], p2, va.y);
            fma2(o2[2][2], p2, vb.x); fma2(o2[2][3], p2, vb.y);
            fma2(o2[3][0], p3, va.x); fma2(o2[3][1], p3, va.y);
            fma2(o2[3][2], p3, vb.x); fma2(o2[3][3], p3, vb.y);
        }
        __syncthreads();
    }

    #pragma unroll
    for (int i = 0; i < 4; i++) {
        float inv = 1.0f / l[i];
        int row = q0 + ty*4 + i;
        float* yp = Y + ((size_t)(b*SS + row)) * DD + h*HD;
        float2 c0 = unpack2(o2[i][0]);
        float2 c1 = unpack2(o2[i][1]);
        float2 c2 = unpack2(o2[i][2]);
        float2 c3 = unpack2(o2[i][3]);
        float4 lo = make_float4(c0.x*inv, c0.y*inv, c1.x*inv, c1.y*inv);
        float4 hi = make_float4(c2.x*inv, c2.y*inv, c3.x*inv, c3.y*inv);
        *(float4*)(yp + tx*4)      = lo;
        *(float4*)(yp + 64 + tx*4) = hi;
    }
}

// ---------------- launch ----------------------------------------------------
extern "C" void kernel_launch(void* const* d_in, const int* in_sizes, int n_in,
                              void* d_out, int out_size)
{
    const float* x     = (const float*)d_in[0];
    const float* freqs = (const float*)d_in[1];
    const float* wqkv  = (const float*)d_in[2];
    const float* wo    = (const float*)d_in[3];
    const float* qw    = (const float*)d_in[4];
    const float* kw    = (const float*)d_in[5];
    float* out = (float*)d_out;

    float *p_qkv, *p_qt, *p_kt, *p_y;
    cudaGetSymbolAddress((void**)&p_qkv, g_qkv);
    cudaGetSymbolAddress((void**)&p_qt,  g_qt);
    cudaGetSymbolAddress((void**)&p_kt,  g_kt);
    cudaGetSymbolAddress((void**)&p_y,   g_y);

    // 1) QKV projection: [4096,3072] = x[4096,2048] * wqkv[3072,2048]^T
    gemm_nt<<<dim3(QKVE/GBN, (BB*SS)/GBM), 256>>>(x, wqkv, p_qkv,
                                                  BB*SS, QKVE, DD);

    // 2) RMSNorm + RoPE + transpose (Q pre-scaled); V stays in g_qkv
    norm_rope_t<<<dim3(SS/32, NH + NKV, BB), 256>>>(p_qkv, freqs, qw, kw,
                                                    p_qt, p_kt);

    // 3) Flash attention (causal, GQA)
    cudaFuncSetAttribute(flash_kernel,
                         cudaFuncAttributeMaxDynamicSharedMemorySize, FLASH_SMEM);
    flash_kernel<<<dim3(SS/64, NH, BB), 256, FLASH_SMEM>>>(p_qt, p_kt, p_qkv, p_y);

    // 4) Output projection: out[4096,2048] = y[4096,2048] * wo[2048,2048]^T
    gemm_nt<<<dim3(DD/GBN, (BB*SS)/GBM), 256>>>(p_y, wo, out,
                                                BB*SS, DD, NH*HD);
}

// round 4
// speedup vs baseline: 1.4114x; 1.0215x over previous
#include <cuda_runtime.h>
#include <math.h>

// Problem constants
#define BB   2
#define SS   2048
#define DD   2048
#define NH   16
#define NKV  4
#define HD   128
#define EHEADS (NH + 2*NKV)          // 24
#define QKVE (EHEADS * HD)           // 3072

// ---------------- scratch (device globals; no allocation allowed) ----------
__device__ __align__(16) float g_qkv[(size_t)BB * SS * QKVE];     // [4096][3072]
__device__ __align__(16) float g_qt [(size_t)BB * NH  * HD * SS]; // [B][NH][HD][S]
__device__ __align__(16) float g_kt [(size_t)BB * NKV * HD * SS]; // [B][NKV][HD][S]
__device__ __align__(16) float g_y  [(size_t)BB * SS * DD];       // [4096][2048]

// ---------------- packed f32x2 helpers -------------------------------------
__device__ __forceinline__ unsigned long long pack2(float x) {
    unsigned long long r;
    asm("mov.b64 %0, {%1, %1};" : "=l"(r) : "f"(x));
    return r;
}
__device__ __forceinline__ void fma2(unsigned long long& c,
                                     unsigned long long a,
                                     unsigned long long b) {
    asm("fma.rn.f32x2 %0, %1, %2, %0;" : "+l"(c) : "l"(a), "l"(b));
}
__device__ __forceinline__ void mul2(unsigned long long& c, unsigned long long a) {
    asm("mul.rn.f32x2 %0, %0, %1;" : "+l"(c) : "l"(a));
}
__device__ __forceinline__ float2 unpack2(unsigned long long v) {
    float2 r;
    asm("mov.b64 {%0, %1}, %2;" : "=f"(r.x), "=f"(r.y) : "l"(v));
    return r;
}
__device__ __forceinline__ float ex2f(float x) {
    float y;
    asm("ex2.approx.ftz.f32 %0, %1;" : "=f"(y) : "f"(x));
    return y;
}

// ---------------- GEMM: C[M,N] = A[M,K] * B[N,K]^T  (both K-major) ----------
#define GBM 128
#define GBN 128
#define GBK 16
#define GAS (GBM + 4)   // padded row stride (floats)

__global__ void __launch_bounds__(256) gemm_nt(const float* __restrict__ A,
                                               const float* __restrict__ B,
                                               float* __restrict__ C,
                                               int M, int N, int K)
{
    __shared__ __align__(16) float As[2][GBK * GAS];
    __shared__ __align__(16) float Bs[2][GBK * GAS];

    const int tid  = threadIdx.x;
    const int bm   = blockIdx.y * GBM;
    const int bn   = blockIdx.x * GBN;
    const int lrow = tid >> 2;          // 0..63
    const int lk4  = (tid & 3) << 2;    // 0,4,8,12

    const float* Ap = A + (size_t)(bm + lrow) * K + lk4;
    const float* Bp = B + (size_t)(bn + lrow) * K + lk4;
    const size_t rowoff = (size_t)64 * K;

    unsigned long long acc[8][4];
    #pragma unroll
    for (int i = 0; i < 8; i++)
        #pragma unroll
        for (int j = 0; j < 4; j++)
            acc[i][j] = 0ull;

    const int ty = tid >> 4, tx = tid & 15;
    const int nk = K / GBK;

    float4 a0 = *(const float4*)Ap;
    float4 a1 = *(const float4*)(Ap + rowoff);
    float4 b0 = *(const float4*)Bp;
    float4 b1 = *(const float4*)(Bp + rowoff);

    {
        float* Aw = As[0]; float* Bw = Bs[0];
        Aw[(lk4+0)*GAS + lrow]      = a0.x;
        Aw[(lk4+1)*GAS + lrow]      = a0.y;
        Aw[(lk4+2)*GAS + lrow]      = a0.z;
        Aw[(lk4+3)*GAS + lrow]      = a0.w;
        Aw[(lk4+0)*GAS + lrow + 64] = a1.x;
        Aw[(lk4+1)*GAS + lrow + 64] = a1.y;
        Aw[(lk4+2)*GAS + lrow + 64] = a1.z;
        Aw[(lk4+3)*GAS + lrow + 64] = a1.w;
        Bw[(lk4+0)*GAS + lrow]      = b0.x;
        Bw[(lk4+1)*GAS + lrow]      = b0.y;
        Bw[(lk4+2)*GAS + lrow]      = b0.z;
        Bw[(lk4+3)*GAS + lrow]      = b0.w;
        Bw[(lk4+0)*GAS + lrow + 64] = b1.x;
        Bw[(lk4+1)*GAS + lrow + 64] = b1.y;
        Bw[(lk4+2)*GAS + lrow + 64] = b1.z;
        Bw[(lk4+3)*GAS + lrow + 64] = b1.w;
    }
    __syncthreads();

    for (int t = 0; t < nk; ++t) {
        const int cur = t & 1;
        if (t + 1 < nk) {
            Ap += GBK; Bp += GBK;
            a0 = *(const float4*)Ap;
            a1 = *(const float4*)(Ap + rowoff);
            b0 = *(const float4*)Bp;
            b1 = *(const float4*)(Bp + rowoff);
        }

        const float* Ar = As[cur];
        const float* Br = Bs[cur];
        #pragma unroll
        for (int k = 0; k < GBK; ++k) {
            const float* arow = &Ar[k*GAS + ty*8];
            float4 af0 = *(const float4*)(arow);
            float4 af1 = *(const float4*)(arow + 4);
            ulonglong2 bl0 = *(const ulonglong2*)&Br[k*GAS + tx*4];
            ulonglong2 bl1 = *(const ulonglong2*)&Br[k*GAS + 64 + tx*4];

            unsigned long long av[8];
            av[0] = pack2(af0.x); av[1] = pack2(af0.y);
            av[2] = pack2(af0.z); av[3] = pack2(af0.w);
            av[4] = pack2(af1.x); av[5] = pack2(af1.y);
            av[6] = pack2(af1.z); av[7] = pack2(af1.w);
            unsigned long long bv[4] = {bl0.x, bl0.y, bl1.x, bl1.y};

            #pragma unroll
            for (int i = 0; i < 8; i++)
                #pragma unroll
                for (int jp = 0; jp < 4; jp++)
                    fma2(acc[i][jp], av[i], bv[jp]);
        }

        if (t + 1 < nk) {
            const int nxt = (t + 1) & 1;
            float* Aw = As[nxt]; float* Bw = Bs[nxt];
            Aw[(lk4+0)*GAS + lrow]      = a0.x;
            Aw[(lk4+1)*GAS + lrow]      = a0.y;
            Aw[(lk4+2)*GAS + lrow]      = a0.z;
            Aw[(lk4+3)*GAS + lrow]      = a0.w;
            Aw[(lk4+0)*GAS + lrow + 64] = a1.x;
            Aw[(lk4+1)*GAS + lrow + 64] = a1.y;
            Aw[(lk4+2)*GAS + lrow + 64] = a1.z;
            Aw[(lk4+3)*GAS + lrow + 64] = a1.w;
            Bw[(lk4+0)*GAS + lrow]      = b0.x;
            Bw[(lk4+1)*GAS + lrow]      = b0.y;
            Bw[(lk4+2)*GAS + lrow]      = b0.z;
            Bw[(lk4+3)*GAS + lrow]      = b0.w;
            Bw[(lk4+0)*GAS + lrow + 64] = b1.x;
            Bw[(lk4+1)*GAS + lrow + 64] = b1.y;
            Bw[(lk4+2)*GAS + lrow + 64] = b1.z;
            Bw[(lk4+3)*GAS + lrow + 64] = b1.w;
        }
        __syncthreads();
    }

    #pragma unroll
    for (int i = 0; i < 8; i++) {
        float2 c0 = unpack2(acc[i][0]);
        float2 c1 = unpack2(acc[i][1]);
        float2 c2 = unpack2(acc[i][2]);
        float2 c3 = unpack2(acc[i][3]);
        float* cp = C + (size_t)(bm + ty*8 + i) * N + bn;
        *(float4*)(cp + tx*4)      = make_float4(c0.x, c0.y, c1.x, c1.y);
        *(float4*)(cp + 64 + tx*4) = make_float4(c2.x, c2.y, c3.x, c3.y);
    }
}

// ---------------- RMSNorm + RoPE + transpose to [B,H][HD][S] ----------------
#define QSCALE 0.12751943f   // (1/sqrt(128)) * log2(e)
__global__ void __launch_bounds__(256) norm_rope_t(const float* __restrict__ qkv,
                                                   const float* __restrict__ freqs,
                                                   const float* __restrict__ qw,
                                                   const float* __restrict__ kw,
                                                   float* __restrict__ qt,
                                                   float* __restrict__ kt)
{
    __shared__ float st[128 * 33];
    const int s0   = blockIdx.x * 32;
    const int h    = blockIdx.y;
    const int b    = blockIdx.z;
    const int w    = threadIdx.x >> 5;
    const int lane = threadIdx.x & 31;
    const bool isq = (h < NH);
    const float fold = isq ? QSCALE : 1.0f;
    const float* wn  = isq ? qw : kw;
    const float4 wv  = *(const float4*)(wn + lane*4);

    #pragma unroll
    for (int ii = 0; ii < 4; ii++) {
        const int sl = w*4 + ii;
        const int s  = s0 + sl;
        const float* src = qkv + ((size_t)(b*SS + s)) * QKVE + h * HD;
        float4 v = *(const float4*)(src + lane*4);
        float ssum = v.x*v.x + v.y*v.y + v.z*v.z + v.w*v.w;
        #pragma unroll
        for (int off = 16; off >= 1; off >>= 1)
            ssum += __shfl_xor_sync(0xffffffffu, ssum, off);
        float inv = rsqrtf(ssum * (1.0f / HD) + 1e-6f) * fold;
        float x0 = v.x * inv * wv.x;
        float x1 = v.y * inv * wv.y;
        float x2 = v.z * inv * wv.z;
        float x3 = v.w * inv * wv.w;
        float4 f = *(const float4*)(freqs + (size_t)s*128 + lane*4);
        st[(lane*4+0)*33 + sl] = x0*f.x - x1*f.y;
        st[(lane*4+1)*33 + sl] = x1*f.x + x0*f.y;
        st[(lane*4+2)*33 + sl] = x2*f.z - x3*f.w;
        st[(lane*4+3)*33 + sl] = x3*f.z + x2*f.w;
    }
    __syncthreads();

    float* dst = isq ? (qt + ((size_t)(b*NH  + h))      * HD * SS)
                     : (kt + ((size_t)(b*NKV + h - NH)) * HD * SS);
    #pragma unroll
    for (int it = 0; it < 4; it++) {
        int lin = threadIdx.x + it*256;
        int d   = lin >> 3;
        int sl4 = (lin & 7) << 2;
        float4 o = make_float4(st[d*33 + sl4 + 0], st[d*33 + sl4 + 1],
                               st[d*33 + sl4 + 2], st[d*33 + sl4 + 3]);
        *(float4*)(dst + (size_t)d*SS + s0 + sl4) = o;
    }
}

// ---------------- Flash attention (causal, GQA), BM=128 BN=64 ---------------
#define FRS 132   // row-stride for Qs [d][r] and Ps [c][r] (128 rows + 4 pad)
#define FKS 68    // col-stride for Ks [d][c] (64 cols + 4 pad)
#define FVS 132   // d-stride  for Vs [kk][d]
#define FLASH_SMEM ((128*FRS + 128*FKS + 64*FVS + 64*FRS) * 4)   // 169984 B

__global__ void __launch_bounds__(256) flash_kernel(const float* __restrict__ Qt,
                                                    const float* __restrict__ Kt,
                                                    const float* __restrict__ qkv,
                                                    float* __restrict__ Y)
{
    extern __shared__ __align__(16) float sm[];
    float* Qs = sm;                    // [d][r]  128 x 132 (pre-scaled)
    float* Ks = Qs + 128*FRS;          // [d][c]  128 x 68
    float* Vs = Ks + 128*FKS;          // [kk][d]  64 x 132
    float* Ps = Vs + 64*FVS;           // [c][r]   64 x 132

    const int tid = threadIdx.x;
    const int qb  = gridDim.x - 1 - blockIdx.x;   // long blocks first
    const int h   = blockIdx.y;
    const int b   = blockIdx.z;
    const int q0  = qb * 128;

    const float* qsrc = Qt  + ((size_t)(b*NH  + h)        * HD) * SS + q0;
    const float* ksrc = Kt  + ((size_t)(b*NKV + (h >> 2)) * HD) * SS;
    const float* vsrc = qkv + ((size_t)b*SS) * QKVE + (NH + NKV + (h >> 2)) * HD;

    // Q tile 128d x 128r (transposed in global; coalesced copy)
    #pragma unroll
    for (int it = 0; it < 16; it++) {
        int lin = tid + it*256;
        int d   = lin >> 5;
        int r4  = (lin & 31) << 2;
        *(float4*)&Qs[d*FRS + r4] = *(const float4*)(qsrc + (size_t)d*SS + r4);
    }

    const int ty = tid >> 4, tx = tid & 15;
    // 8 rows per thread: rows (i<4 ? ty*4+i : 64+ty*4+i-4); 8 cols (pairs) per row
    unsigned long long o2[8][4];
    float m[8], l[8];
    #pragma unroll
    for (int i = 0; i < 8; i++) {
        m[i] = -1e30f; l[i] = 0.f;
        #pragma unroll
        for (int j = 0; j < 4; j++) o2[i][j] = 0ull;
    }
    __syncthreads();

    const int nkb = 2*qb + 2;
    for (int kb = 0; kb < nkb; ++kb) {
        const int k0 = kb * 64;
        // K tile 128d x 64c ; V tile 64kk x 128d
        #pragma unroll
        for (int it = 0; it < 8; it++) {
            int lin = tid + it*256;
            int d   = lin >> 4;
            int c4  = (lin & 15) << 2;
            *(float4*)&Ks[d*FKS + c4] = *(const float4*)(ksrc + (size_t)d*SS + k0 + c4);
            int r   = lin >> 5;
            int d4  = (lin & 31) << 2;
            *(float4*)&Vs[r*FVS + d4] = *(const float4*)(vsrc + (size_t)(k0 + r)*QKVE + d4);
        }
        __syncthreads();

        // QK^T
        unsigned long long acc[4][4];   // [row-pair][col j]; pairs (0,1)(2,3)(64,65)(66,67)
        #pragma unroll
        for (int p = 0; p < 4; p++)
            #pragma unroll
            for (int j = 0; j < 4; j++) acc[p][j] = 0ull;

        #pragma unroll 2
        for (int d = 0; d < 128; ++d) {
            ulonglong2 qa = *(const ulonglong2*)&Qs[d*FRS + ty*4];
            ulonglong2 qc = *(const ulonglong2*)&Qs[d*FRS + 64 + ty*4];
            float4 kk4 = *(const float4*)&Ks[d*FKS + tx*4];
            unsigned long long b0 = pack2(kk4.x), b1 = pack2(kk4.y);
            unsigned long long b2 = pack2(kk4.z), b3 = pack2(kk4.w);
            fma2(acc[0][0], qa.x, b0); fma2(acc[1][0], qa.y, b0);
            fma2(acc[0][1], qa.x, b1); fma2(acc[1][1], qa.y, b1);
            fma2(acc[0][2], qa.x, b2); fma2(acc[1][2], qa.y, b2);
            fma2(acc[0][3], qa.x, b3); fma2(acc[1][3], qa.y, b3);
            fma2(acc[2][0], qc.x, b0); fma2(acc[3][0], qc.y, b0);
            fma2(acc[2][1], qc.x, b1); fma2(acc[3][1], qc.y, b1);
            fma2(acc[2][2], qc.x, b2); fma2(acc[3][2], qc.y, b2);
            fma2(acc[2][3], qc.x, b3); fma2(acc[3][3], qc.y, b3);
        }

        float s[8][4];
        #pragma unroll
        for (int p = 0; p < 4; p++)
            #pragma unroll
            for (int j = 0; j < 4; j++) {
                float2 v = unpack2(acc[p][j]);
                s[p*2+0][j] = v.x;
                s[p*2+1][j] = v.y;
            }

        if (kb >= 2*qb) {   // causal mask on the last two k-tiles
            #pragma unroll
            for (int i = 0; i < 8; i++) {
                int row = (i < 4) ? (ty*4 + i) : (64 + ty*4 + i - 4);
                #pragma unroll
                for (int j = 0; j < 4; j++)
                    if (k0 + tx*4 + j > q0 + row) s[i][j] = -1e30f;
            }
        }

        // online softmax in log2 domain (Q pre-scaled by scale*log2e)
        #pragma unroll
        for (int i = 0; i < 8; i++) {
            float mx = fmaxf(fmaxf(s[i][0], s[i][1]), fmaxf(s[i][2], s[i][3]));
            #pragma unroll
            for (int off = 8; off >= 1; off >>= 1)
                mx = fmaxf(mx, __shfl_xor_sync(0xffffffffu, mx, off, 16));
            float mn   = fmaxf(m[i], mx);
            float corr = ex2f(m[i] - mn);
            m[i] = mn;
            float rs = 0.f;
            #pragma unroll
            for (int j = 0; j < 4; j++) {
                float p = ex2f(s[i][j] - mn);
                s[i][j] = p;
                rs += p;
            }
            #pragma unroll
            for (int off = 8; off >= 1; off >>= 1)
                rs += __shfl_xor_sync(0xffffffffu, rs, off, 16);
            l[i] = l[i] * corr + rs;
            unsigned long long c2 = pack2(corr);
            #pragma unroll
            for (int j = 0; j < 4; j++) mul2(o2[i][j], c2);
        }

        // store P transposed [c][r]
        #pragma unroll
        for (int j = 0; j < 4; j++) {
            *(float4*)&Ps[(tx*4 + j)*FRS + ty*4]
                = make_float4(s[0][j], s[1][j], s[2][j], s[3][j]);
            *(float4*)&Ps[(tx*4 + j)*FRS + 64 + ty*4]
                = make_float4(s[4][j], s[5][j], s[6][j], s[7][j]);
        }
        __syncthreads();

        // O += P * V
        #pragma unroll 2
        for (int kk = 0; kk < 64; ++kk) {
            float4 pa = *(const float4*)&Ps[kk*FRS + ty*4];
            float4 pc = *(const float4*)&Ps[kk*FRS + 64 + ty*4];
            ulonglong2 va = *(const ulonglong2*)&Vs[kk*FVS + tx*4];
            ulonglong2 vb = *(const ulonglong2*)&Vs[kk*FVS + 64 + tx*4];
            unsigned long long p0 = pack2(pa.x), p1 = pack2(pa.y);
            unsigned long long p2 = pack2(pa.z), p3 = pack2(pa.w);
            unsigned long long p4 = pack2(pc.x), p5 = pack2(pc.y);
            unsigned long long p6 = pack2(pc.z), p7 = pack2(pc.w);
            fma2(o2[0][0], p0, va.x); fma2(o2[0][1], p0, va.y);
            fma2(o2[0][2], p0, vb.x); fma2(o2[0][3], p0, vb.y);
            fma2(o2[1][0], p1, va.x); fma2(o2[1][1], p1, va.y);
            fma2(o2[1][2], p1, vb.x); fma2(o2[1][3], p1, vb.y);
            fma2(o2[2][0], p2, va.x); fma2(o2[2][1], p2, va.y);
            fma2(o2[2][2], p2, vb.x); fma2(o2[2][3], p2, vb.y);
            fma2(o2[3][0], p3, va.x); fma2(o2[3][1], p3, va.y);
            fma2(o2[3][2], p3, vb.x); fma2(o2[3][3], p3, vb.y);
            fma2(o2[4][0], p4, va.x); fma2(o2[4][1], p4, va.y);
            fma2(o2[4][2], p4, vb.x); fma2(o2[4][3], p4, vb.y);
            fma2(o2[5][0], p5, va.x); fma2(o2[5][1], p5, va.y);
            fma2(o2[5][2], p5, vb.x); fma2(o2[5][3], p5, vb.y);
            fma2(o2[6][0], p6, va.x); fma2(o2[6][1], p6, va.y);
            fma2(o2[6][2], p6, vb.x); fma2(o2[6][3], p6, vb.y);
            fma2(o2[7][0], p7, va.x); fma2(o2[7][1], p7, va.y);
            fma2(o2[7][2], p7, vb.x); fma2(o2[7][3], p7, vb.y);
        }
        __syncthreads();
    }

    #pragma unroll
    for (int i = 0; i < 8; i++) {
        float inv = 1.0f / l[i];
        int row = q0 + ((i < 4) ? (ty*4 + i) : (64 + ty*4 + i - 4));
        float* yp = Y + ((size_t)(b*SS + row)) * DD + h*HD;
        float2 c0 = unpack2(o2[i][0]);
        float2 c1 = unpack2(o2[i][1]);
        float2 c2 = unpack2(o2[i][2]);
        float2 c3 = unpack2(o2[i][3]);
        *(float4*)(yp + tx*4)      = make_float4(c0.x*inv, c0.y*inv, c1.x*inv, c1.y*inv);
        *(float4*)(yp + 64 + tx*4) = make_float4(c2.x*inv, c2.y*inv, c3.x*inv, c3.y*inv);
    }
}

// ---------------- launch ----------------------------------------------------
extern "C" void kernel_launch(void* const* d_in, const int* in_sizes, int n_in,
                              void* d_out, int out_size)
{
    const float* x     = (const float*)d_in[0];
    const float* freqs = (const float*)d_in[1];
    const float* wqkv  = (const float*)d_in[2];
    const float* wo    = (const float*)d_in[3];
    const float* qw    = (const float*)d_in[4];
    const float* kw    = (const float*)d_in[5];
    float* out = (float*)d_out;

    float *p_qkv, *p_qt, *p_kt, *p_y;
    cudaGetSymbolAddress((void**)&p_qkv, g_qkv);
    cudaGetSymbolAddress((void**)&p_qt,  g_qt);
    cudaGetSymbolAddress((void**)&p_kt,  g_kt);
    cudaGetSymbolAddress((void**)&p_y,   g_y);

    // 1) QKV projection: [4096,3072] = x[4096,2048] * wqkv[3072,2048]^T
    gemm_nt<<<dim3(QKVE/GBN, (BB*SS)/GBM), 256>>>(x, wqkv, p_qkv,
                                                  BB*SS, QKVE, DD);

    // 2) RMSNorm + RoPE + transpose (Q pre-scaled); V stays in g_qkv
    norm_rope_t<<<dim3(SS/32, NH + NKV, BB), 256>>>(p_qkv, freqs, qw, kw,
                                                    p_qt, p_kt);

    // 3) Flash attention (causal, GQA), BM=128
    cudaFuncSetAttribute(flash_kernel,
                         cudaFuncAttributeMaxDynamicSharedMemorySize, FLASH_SMEM);
    flash_kernel<<<dim3(SS/128, NH, BB), 256, FLASH_SMEM>>>(p_qt, p_kt, p_qkv, p_y);

    // 4) Output projection: out[4096,2048] = y[4096,2048] * wo[2048,2048]^T
    gemm_nt<<<dim3(DD/GBN, (BB*SS)/GBM), 256>>>(p_y, wo, out,
                                                BB*SS, DD, NH*HD);
}